// round 2
// baseline (speedup 1.0000x reference)
#include <cuda_runtime.h>
#include <math_constants.h>

// NeighborsValuesAssigner: x(32,3,64,64), patches(2048,3,5,5), values(2048,128)
// out(32,128,64,64) fp32.
// dist[b,n,h,w] = 0.5*||p_n||^2 - <p_n, window(x,b,h,w)>; top-8 smallest per
// position; out = mean of values[idx] over the 8 neighbors.

#define BB 32
#define CC 3
#define HW 64
#define NN 2048
#define DD 128
#define KNN 8
#define KVOL 75          // 3*5*5
#define KPAD 76          // padded: slot 75 carries bias (x side = 1.0)
#define NP 128           // patches per smem chunk
#define NCHUNK (NN / NP) // 16
#define NPOS (BB * HW * HW) // 131072

__device__ float g_bias[NN];
__device__ int g_topk[NPOS * KNN];

// ---------------------------------------------------------------------------
// Kernel 1: bias_n = 0.5 * sum(p^2)
// ---------------------------------------------------------------------------
__global__ void bias_kernel(const float* __restrict__ patches) {
    int n = blockIdx.x * blockDim.x + threadIdx.x;
    if (n < NN) {
        const float* p = patches + n * KVOL;
        float s = 0.f;
#pragma unroll
        for (int i = 0; i < KVOL; i++) {
            float v = p[i];
            s = fmaf(v, v, s);
        }
        g_bias[n] = 0.5f * s;
    }
}

// ---------------------------------------------------------------------------
// Kernel 2: fused distance-GEMM + top-8 selection.
// 1 thread = 1 spatial position. x-window (75 vals + trailing 1.0) lives in
// registers as 38 packed f32x2 pairs. Negated patch chunk staged in smem with
// rows padded to 76 floats (19 float4s, slot 75 = bias) so the inner loop is
// 19 x LDS.128 broadcast + 38 x fma.rn.f32x2 per patch.
// ---------------------------------------------------------------------------
__global__ void __launch_bounds__(256, 2)
dist_topk_kernel(const float* __restrict__ x, const float* __restrict__ patches) {
    __shared__ float sp[NP * KPAD]; // negated patches, row slot 75 = bias

    int pos = blockIdx.x * 256 + threadIdx.x;
    int w = pos & 63;
    int h = (pos >> 6) & 63;
    int b = pos >> 12;

    // ---- load x window (zero-padded), append 1.0 for the bias slot ----
    float xv[KPAD];
#pragma unroll
    for (int c = 0; c < CC; c++) {
#pragma unroll
        for (int kh = 0; kh < 5; kh++) {
            int hy = h + kh - 2;
            bool rok = (hy >= 0) && (hy < HW);
#pragma unroll
            for (int kw = 0; kw < 5; kw++) {
                int wx = w + kw - 2;
                float v = 0.f;
                if (rok && wx >= 0 && wx < HW)
                    v = x[((b * CC + c) * HW + hy) * HW + wx];
                xv[(c * 5 + kh) * 5 + kw] = v;
            }
        }
    }
    xv[75] = 1.0f;

    // pack into 38 x 64-bit pairs (register-resident)
    unsigned long long xp[38];
#pragma unroll
    for (int j = 0; j < 38; j++) {
        asm("mov.b64 %0, {%1,%2};" : "=l"(xp[j]) : "f"(xv[2 * j]), "f"(xv[2 * j + 1]));
    }

    // top-8 (sorted ascending)
    float bestd[KNN];
    int besti[KNN];
#pragma unroll
    for (int j = 0; j < KNN; j++) { bestd[j] = 3.0e38f; besti[j] = 0; }

    for (int ch = 0; ch < NCHUNK; ch++) {
        __syncthreads();
        // stage negated patch chunk; slot 75 gets the bias term
        const float* pg = patches + ch * NP * KVOL;
        for (int i = threadIdx.x; i < NP * KVOL; i += 256) {
            int n = i / KVOL;
            int r = i - n * KVOL;
            sp[n * KPAD + r] = -pg[i];
        }
        for (int i = threadIdx.x; i < NP; i += 256) {
            sp[i * KPAD + 75] = g_bias[ch * NP + i];
        }
        __syncthreads();

#pragma unroll 2
        for (int n = 0; n < NP; n++) {
            const ulonglong2* pr =
                reinterpret_cast<const ulonglong2*>(sp + n * KPAD);
            unsigned long long acc0, acc1;
            asm("mov.b64 %0, {%1,%2};" : "=l"(acc0) : "f"(0.f), "f"(0.f));
            asm("mov.b64 %0, {%1,%2};" : "=l"(acc1) : "f"(0.f), "f"(0.f));
#pragma unroll
            for (int j = 0; j < 19; j++) {
                ulonglong2 q = pr[j]; // LDS.128 broadcast
                asm("fma.rn.f32x2 %0, %1, %2, %0;"
                    : "+l"(acc0) : "l"(q.x), "l"(xp[2 * j]));
                asm("fma.rn.f32x2 %0, %1, %2, %0;"
                    : "+l"(acc1) : "l"(q.y), "l"(xp[2 * j + 1]));
            }
            float a0l, a0h, a1l, a1h;
            asm("mov.b64 {%0,%1}, %2;" : "=f"(a0l), "=f"(a0h) : "l"(acc0));
            asm("mov.b64 {%0,%1}, %2;" : "=f"(a1l), "=f"(a1h) : "l"(acc1));
            float dist = (a0l + a0h) + (a1l + a1h);

            bool ins = dist < bestd[KNN - 1];
            if (__any_sync(0xffffffffu, ins)) {
                // branchless compare-carry ladder; no-op for c = +INF lanes
                float c = ins ? dist : CUDART_INF_F;
                int ci = ch * NP + n;
#pragma unroll
                for (int j = 0; j < KNN; j++) {
                    float dj = bestd[j];
                    int ij = besti[j];
                    bool lt = c < dj;
                    bestd[j] = lt ? c : dj;
                    besti[j] = lt ? ci : ij;
                    c = lt ? dj : c;
                    ci = lt ? ij : ci;
                }
            }
        }
    }

    int* dst = g_topk + pos * KNN;
#pragma unroll
    for (int j = 0; j < KNN; j++) dst[j] = besti[j];
}

// ---------------------------------------------------------------------------
// Kernel 3: gather + mean with coalesced reads and writes via smem transpose.
// ---------------------------------------------------------------------------
__global__ void __launch_bounds__(256)
gather_kernel(const float* __restrict__ values, float* __restrict__ out) {
    __shared__ float ssum[32][133]; // pad 133: conflict-free column reads

    int bh = blockIdx.x;      // b*64 + h
    int wt = blockIdx.y;      // 0..1
    int b = bh >> 6;
    int h = bh & 63;
    int w0 = wt * 32;

    int warp = threadIdx.x >> 5;
    int lane = threadIdx.x & 31;
    const float4* v4 = reinterpret_cast<const float4*>(values);

#pragma unroll
    for (int r = 0; r < 4; r++) {
        int pl = warp + r * 8; // local position 0..31
        int pos = (bh * HW) + w0 + pl;
        const int* ip = g_topk + pos * KNN;
        float4 a = make_float4(0.f, 0.f, 0.f, 0.f);
#pragma unroll
        for (int k = 0; k < KNN; k++) {
            int idx = ip[k]; // uniform across warp
            float4 v = v4[idx * (DD / 4) + lane];
            a.x += v.x; a.y += v.y; a.z += v.z; a.w += v.w;
        }
        ssum[pl][lane * 4 + 0] = a.x * 0.125f;
        ssum[pl][lane * 4 + 1] = a.y * 0.125f;
        ssum[pl][lane * 4 + 2] = a.z * 0.125f;
        ssum[pl][lane * 4 + 3] = a.w * 0.125f;
    }
    __syncthreads();

    int wl = threadIdx.x & 31;
    int d0 = threadIdx.x >> 5; // 0..7
#pragma unroll
    for (int d = d0; d < DD; d += 8) {
        out[((b * DD + d) * HW + h) * HW + w0 + wl] = ssum[wl][d];
    }
}

// ---------------------------------------------------------------------------
extern "C" void kernel_launch(void* const* d_in, const int* in_sizes, int n_in,
                              void* d_out, int out_size) {
    const float* x = (const float*)d_in[0];       // (32,3,64,64)
    const float* patches = (const float*)d_in[1]; // (2048,3,5,5)
    const float* values = (const float*)d_in[2];  // (2048,128)
    float* out = (float*)d_out;                   // (32,128,64,64)

    bias_kernel<<<(NN + 255) / 256, 256>>>(patches);
    dist_topk_kernel<<<NPOS / 256, 256>>>(x, patches);
    gather_kernel<<<dim3(BB * HW, 2), 256>>>(values, out);
}

// round 3
// speedup vs baseline: 1.1164x; 1.1164x over previous
#include <cuda_runtime.h>
#include <math_constants.h>

// NeighborsValuesAssigner: x(32,3,64,64), patches(2048,3,5,5), values(2048,128)
// out(32,128,64,64) fp32.
// dist[b,n,h,w] = 0.5*||p_n||^2 - <p_n, window(x,b,h,w)>; top-8 smallest per
// position; out = mean of values[idx] over the 8 neighbors.

#define BB 32
#define CC 3
#define HW 64
#define NN 2048
#define DD 128
#define KNN 8
#define KVOL 75          // 3*5*5
#define KPAD 76          // padded: slot 75 carries bias (x side = 1.0)
#define NP 128           // patches per smem chunk
#define NCHUNK (NN / NP) // 16
#define NPOS (BB * HW * HW) // 131072
#define TPB 128          // threads per block (dist kernel)
#define PPT 2            // positions per thread

__device__ float g_bias[NN];
__device__ int g_topk[NPOS * KNN];

// ---------------------------------------------------------------------------
// Kernel 1: bias_n = 0.5 * sum(p^2)
// ---------------------------------------------------------------------------
__global__ void bias_kernel(const float* __restrict__ patches) {
    int n = blockIdx.x * blockDim.x + threadIdx.x;
    if (n < NN) {
        const float* p = patches + n * KVOL;
        float s = 0.f;
#pragma unroll
        for (int i = 0; i < KVOL; i++) {
            float v = p[i];
            s = fmaf(v, v, s);
        }
        g_bias[n] = 0.5f * s;
    }
}

// ---------------------------------------------------------------------------
// Kernel 2: fused distance-GEMM + top-8.
// 1 thread = 2 adjacent spatial positions (w even, w+1). Both x-windows are
// register-resident as 38 packed f32x2 pairs each. A patch chunk (negated,
// bias in slot 75) is staged in smem; the inner loop loads each patch
// element-pair ONCE (LDS.64 broadcast) and feeds two fma.rn.f32x2 chains,
// halving smem traffic per position vs one-position-per-thread.
// ---------------------------------------------------------------------------
__global__ void __launch_bounds__(TPB, 2)
dist_topk_kernel(const float* __restrict__ x, const float* __restrict__ patches) {
    __shared__ float sp[NP * KPAD]; // negated patches, row slot 75 = bias

    int gtid = blockIdx.x * TPB + threadIdx.x;
    int pos0 = gtid * PPT;          // even w
    int w0 = pos0 & 63;
    int h = (pos0 >> 6) & 63;
    int b = pos0 >> 12;

    // ---- load both x windows (zero-padded), append 1.0 for the bias slot ----
    float xv0[KPAD], xv1[KPAD];
#pragma unroll
    for (int c = 0; c < CC; c++) {
#pragma unroll
        for (int kh = 0; kh < 5; kh++) {
            int hy = h + kh - 2;
            bool rok = (hy >= 0) && (hy < HW);
            const float* xrow = x + ((b * CC + c) * HW + hy) * HW;
#pragma unroll
            for (int kw = 0; kw < 5; kw++) {
                int wa = w0 + kw - 2;
                int wb = wa + 1;
                float va = 0.f, vb = 0.f;
                if (rok && wa >= 0 && wa < HW) va = xrow[wa];
                if (rok && wb >= 0 && wb < HW) vb = xrow[wb];
                xv0[(c * 5 + kh) * 5 + kw] = va;
                xv1[(c * 5 + kh) * 5 + kw] = vb;
            }
        }
    }
    xv0[75] = 1.0f;
    xv1[75] = 1.0f;

    // pack into 2 x 38 64-bit pairs (register-resident)
    unsigned long long xpA[38], xpB[38];
#pragma unroll
    for (int j = 0; j < 38; j++) {
        asm("mov.b64 %0, {%1,%2};" : "=l"(xpA[j]) : "f"(xv0[2 * j]), "f"(xv0[2 * j + 1]));
        asm("mov.b64 %0, {%1,%2};" : "=l"(xpB[j]) : "f"(xv1[2 * j]), "f"(xv1[2 * j + 1]));
    }

    // top-8 per position (sorted ascending)
    float bd0[KNN], bd1[KNN];
    int bi0[KNN], bi1[KNN];
#pragma unroll
    for (int j = 0; j < KNN; j++) {
        bd0[j] = 3.0e38f; bi0[j] = 0;
        bd1[j] = 3.0e38f; bi1[j] = 0;
    }

    for (int ch = 0; ch < NCHUNK; ch++) {
        __syncthreads();
        // stage negated patch chunk; slot 75 gets the bias term
        const float* pg = patches + ch * NP * KVOL;
        for (int i = threadIdx.x; i < NP * KVOL; i += TPB) {
            int n = i / KVOL;
            int r = i - n * KVOL;
            sp[n * KPAD + r] = -pg[i];
        }
        for (int i = threadIdx.x; i < NP; i += TPB) {
            sp[i * KPAD + 75] = g_bias[ch * NP + i];
        }
        __syncthreads();

        for (int n = 0; n < NP; n++) {
            const unsigned long long* pr =
                reinterpret_cast<const unsigned long long*>(sp + n * KPAD);
            unsigned long long accA, accB;
            asm("mov.b64 %0, {%1,%2};" : "=l"(accA) : "f"(0.f), "f"(0.f));
            asm("mov.b64 %0, {%1,%2};" : "=l"(accB) : "f"(0.f), "f"(0.f));
#pragma unroll
            for (int j = 0; j < 38; j++) {
                unsigned long long q = pr[j]; // LDS.64 broadcast, loaded once
                asm("fma.rn.f32x2 %0, %1, %2, %0;" : "+l"(accA) : "l"(q), "l"(xpA[j]));
                asm("fma.rn.f32x2 %0, %1, %2, %0;" : "+l"(accB) : "l"(q), "l"(xpB[j]));
            }
            float a0l, a0h, a1l, a1h;
            asm("mov.b64 {%0,%1}, %2;" : "=f"(a0l), "=f"(a0h) : "l"(accA));
            asm("mov.b64 {%0,%1}, %2;" : "=f"(a1l), "=f"(a1h) : "l"(accB));
            float d0 = a0l + a0h;
            float d1 = a1l + a1h;
            int pidx = ch * NP + n;

            bool ins0 = d0 < bd0[KNN - 1];
            if (__any_sync(0xffffffffu, ins0)) {
                float c = ins0 ? d0 : CUDART_INF_F;
                int ci = pidx;
#pragma unroll
                for (int j = 0; j < KNN; j++) {
                    float dj = bd0[j]; int ij = bi0[j];
                    bool lt = c < dj;
                    bd0[j] = lt ? c : dj;  bi0[j] = lt ? ci : ij;
                    c = lt ? dj : c;       ci = lt ? ij : ci;
                }
            }
            bool ins1 = d1 < bd1[KNN - 1];
            if (__any_sync(0xffffffffu, ins1)) {
                float c = ins1 ? d1 : CUDART_INF_F;
                int ci = pidx;
#pragma unroll
                for (int j = 0; j < KNN; j++) {
                    float dj = bd1[j]; int ij = bi1[j];
                    bool lt = c < dj;
                    bd1[j] = lt ? c : dj;  bi1[j] = lt ? ci : ij;
                    c = lt ? dj : c;       ci = lt ? ij : ci;
                }
            }
        }
    }

    int* dst = g_topk + pos0 * KNN;
#pragma unroll
    for (int j = 0; j < KNN; j++) dst[j] = bi0[j];
#pragma unroll
    for (int j = 0; j < KNN; j++) dst[KNN + j] = bi1[j];
}

// ---------------------------------------------------------------------------
// Kernel 3: gather + mean with coalesced reads and writes via smem transpose.
// ---------------------------------------------------------------------------
__global__ void __launch_bounds__(256)
gather_kernel(const float* __restrict__ values, float* __restrict__ out) {
    __shared__ float ssum[32][133]; // pad 133: conflict-free column reads

    int bh = blockIdx.x;      // b*64 + h
    int wt = blockIdx.y;      // 0..1
    int b = bh >> 6;
    int h = bh & 63;
    int w0 = wt * 32;

    int warp = threadIdx.x >> 5;
    int lane = threadIdx.x & 31;
    const float4* v4 = reinterpret_cast<const float4*>(values);

#pragma unroll
    for (int r = 0; r < 4; r++) {
        int pl = warp + r * 8; // local position 0..31
        int pos = (bh * HW) + w0 + pl;
        const int* ip = g_topk + pos * KNN;
        float4 a = make_float4(0.f, 0.f, 0.f, 0.f);
#pragma unroll
        for (int k = 0; k < KNN; k++) {
            int idx = ip[k]; // uniform across warp
            float4 v = v4[idx * (DD / 4) + lane];
            a.x += v.x; a.y += v.y; a.z += v.z; a.w += v.w;
        }
        ssum[pl][lane * 4 + 0] = a.x * 0.125f;
        ssum[pl][lane * 4 + 1] = a.y * 0.125f;
        ssum[pl][lane * 4 + 2] = a.z * 0.125f;
        ssum[pl][lane * 4 + 3] = a.w * 0.125f;
    }
    __syncthreads();

    int wl = threadIdx.x & 31;
    int d0 = threadIdx.x >> 5; // 0..7
#pragma unroll
    for (int d = d0; d < DD; d += 8) {
        out[((b * DD + d) * HW + h) * HW + w0 + wl] = ssum[wl][d];
    }
}

// ---------------------------------------------------------------------------
extern "C" void kernel_launch(void* const* d_in, const int* in_sizes, int n_in,
                              void* d_out, int out_size) {
    const float* x = (const float*)d_in[0];       // (32,3,64,64)
    const float* patches = (const float*)d_in[1]; // (2048,3,5,5)
    const float* values = (const float*)d_in[2];  // (2048,128)
    float* out = (float*)d_out;                   // (32,128,64,64)

    bias_kernel<<<(NN + 255) / 256, 256>>>(patches);
    dist_topk_kernel<<<NPOS / (TPB * PPT), TPB>>>(x, patches);
    gather_kernel<<<dim3(BB * HW, 2), 256>>>(values, out);
}